// round 1
// baseline (speedup 1.0000x reference)
#include <cuda_runtime.h>
#include <cstdint>

#define D_MODEL  1024
#define N_CTX    2049
#define B_SZ     2
#define SEQ_LEN  2048
#define M_ROWS   (B_SZ * N_CTX)   /* 4098 */
#define N_HEADS  16
#define D_K      64
#define N_LAYERS 16
#define VOCAB    256

typedef unsigned long long ull;

// ---------------- device scratch (allocation-free rule: __device__ globals) ----------------
__device__ float g_X[M_ROWS * D_MODEL];
__device__ float g_Q[M_ROWS * D_MODEL];
__device__ float g_K[M_ROWS * D_MODEL];
__device__ float g_V[M_ROWS * D_MODEL];
__device__ float g_O[M_ROWS * D_MODEL];

// ---------------- packed f32x2 helpers (sm_103a FFMA2 path) ----------------
__device__ __forceinline__ ull pack2(float x, float y) {
    ull r; asm("mov.b64 %0, {%1, %2};" : "=l"(r) : "f"(x), "f"(y)); return r;
}
__device__ __forceinline__ void fma2(ull& d, ull a, ull b) {
    asm("fma.rn.f32x2 %0, %1, %2, %3;" : "=l"(d) : "l"(a), "l"(b), "l"(d));
}
__device__ __forceinline__ float2 unpack2(ull v) {
    float2 r; asm("mov.b64 {%0, %1}, %2;" : "=f"(r.x), "=f"(r.y) : "l"(v)); return r;
}

// ---------------- embedding (with bos prepend) ----------------
__global__ void embed_kernel(const int* __restrict__ ids, const float* __restrict__ emb) {
    int i = blockIdx.x * blockDim.x + threadIdx.x;
    if (i >= M_ROWS * D_MODEL) return;
    int r = i >> 10;
    int d = i & 1023;
    int b = r / N_CTX;
    int t = r - b * N_CTX;
    int tok = (t == 0) ? 0 : ids[b * SEQ_LEN + (t - 1)];
    g_X[i] = emb[tok * D_MODEL + d];
}

// ---------------- SGEMM: C[M,1024] = A[M,1024] @ Bw[1024,1024] (+ Res) ----------------
// 128x128x16 tile, 256 threads, 8x8 microtile, accumulators packed f32x2 along N.
__global__ __launch_bounds__(256) void sgemm1024(const float* __restrict__ A,
                                                 const float* __restrict__ Bw,
                                                 const float* __restrict__ Res,
                                                 float* __restrict__ C) {
    __shared__ float As[16][128];
    __shared__ float Bs[16][128];
    const int tid = threadIdx.x;
    const int tx = tid & 15;
    const int ty = tid >> 4;
    const int row0 = blockIdx.y * 128;
    const int col0 = blockIdx.x * 128;

    ull c2[8][4];
    #pragma unroll
    for (int i = 0; i < 8; i++)
        #pragma unroll
        for (int j = 0; j < 4; j++) c2[i][j] = 0ULL;

    for (int k0 = 0; k0 < 1024; k0 += 16) {
        __syncthreads();
        // load A tile (transposed into As[k][m])
        #pragma unroll
        for (int it = 0; it < 2; it++) {
            int idx = tid + it * 256;             // 0..511 float4 indices
            int m = idx >> 2;
            int kq = (idx & 3) << 2;
            int gr = row0 + m;
            float4 v = make_float4(0.f, 0.f, 0.f, 0.f);
            if (gr < M_ROWS) v = *(const float4*)&A[(size_t)gr * 1024 + k0 + kq];
            As[kq + 0][m] = v.x; As[kq + 1][m] = v.y;
            As[kq + 2][m] = v.z; As[kq + 3][m] = v.w;
        }
        // load B tile
        #pragma unroll
        for (int it = 0; it < 2; it++) {
            int idx = tid + it * 256;
            int k = idx >> 5;
            int nq = (idx & 31) << 2;
            *(float4*)&Bs[k][nq] = *(const float4*)&Bw[(size_t)(k0 + k) * 1024 + col0 + nq];
        }
        __syncthreads();
        #pragma unroll
        for (int kk = 0; kk < 16; kk++) {
            float4 a0 = *(const float4*)&As[kk][ty * 8];
            float4 a1 = *(const float4*)&As[kk][ty * 8 + 4];
            const ull* bu = (const ull*)&Bs[kk][tx * 8];
            ull b0 = bu[0], b1 = bu[1], b2v = bu[2], b3 = bu[3];
            float av[8] = {a0.x, a0.y, a0.z, a0.w, a1.x, a1.y, a1.z, a1.w};
            #pragma unroll
            for (int i = 0; i < 8; i++) {
                ull ad = pack2(av[i], av[i]);
                fma2(c2[i][0], ad, b0);
                fma2(c2[i][1], ad, b1);
                fma2(c2[i][2], ad, b2v);
                fma2(c2[i][3], ad, b3);
            }
        }
    }
    // epilogue
    #pragma unroll
    for (int i = 0; i < 8; i++) {
        int gr = row0 + ty * 8 + i;
        if (gr >= M_ROWS) continue;
        #pragma unroll
        for (int j = 0; j < 4; j++) {
            float2 cc = unpack2(c2[i][j]);
            int col = col0 + tx * 8 + j * 2;
            if (Res) {
                float2 r = *(const float2*)&Res[(size_t)gr * 1024 + col];
                cc.x += r.x; cc.y += r.y;
            }
            *(float2*)&C[(size_t)gr * 1024 + col] = cc;
        }
    }
}

// ---------------- causal flash attention (fp32, one thread per query) ----------------
#define AKT 16
__global__ __launch_bounds__(256) void attn_kernel(const float* __restrict__ Qm,
                                                    const float* __restrict__ Km,
                                                    const float* __restrict__ Vm,
                                                    float* __restrict__ Om) {
    const int h = blockIdx.y;
    const int b = blockIdx.z;
    int q0 = blockIdx.x * 256;
    if (q0 + 256 > N_CTX) q0 = N_CTX - 256;   // clamp last tile (overlap writes identical values)
    const int q = q0 + threadIdx.x;
    const size_t base = (size_t)b * N_CTX * D_MODEL + h * D_K;

    __shared__ float Ks[AKT][64];
    __shared__ float Vs[AKT][64];

    float qreg[64];
    {
        const float4* qp = (const float4*)(Qm + base + (size_t)q * D_MODEL);
        #pragma unroll
        for (int i = 0; i < 16; i++) {
            float4 t = qp[i];
            qreg[4 * i] = t.x; qreg[4 * i + 1] = t.y;
            qreg[4 * i + 2] = t.z; qreg[4 * i + 3] = t.w;
        }
    }
    float o[64];
    #pragma unroll
    for (int d = 0; d < 64; d++) o[d] = 0.f;
    float mrun = -1e30f, lrun = 0.f;

    const int kmax = q0 + 256;   // largest key any thread in this block needs (<= N_CTX)
    for (int k0 = 0; k0 < kmax; k0 += AKT) {
        __syncthreads();
        {
            int idx = threadIdx.x;               // AKT*64/4 == 256 float4 loads
            int kk = idx >> 4;
            int c4 = (idx & 15) << 2;
            int kg = k0 + kk;
            float4 kv = make_float4(0.f, 0.f, 0.f, 0.f);
            float4 vv = make_float4(0.f, 0.f, 0.f, 0.f);
            if (kg < N_CTX) {
                kv = *(const float4*)(Km + base + (size_t)kg * D_MODEL + c4);
                vv = *(const float4*)(Vm + base + (size_t)kg * D_MODEL + c4);
            }
            *(float4*)&Ks[kk][c4] = kv;
            *(float4*)&Vs[kk][c4] = vv;
        }
        __syncthreads();
        if (k0 <= q) {
            float s[AKT];
            float tmax = -1e30f;
            #pragma unroll
            for (int j = 0; j < AKT; j++) {
                float s0 = 0.f, s1 = 0.f, s2 = 0.f, s3 = 0.f;
                const float4* kp = (const float4*)&Ks[j][0];
                #pragma unroll
                for (int dd = 0; dd < 16; dd++) {
                    float4 k4 = kp[dd];
                    s0 = fmaf(qreg[4 * dd], k4.x, s0);
                    s1 = fmaf(qreg[4 * dd + 1], k4.y, s1);
                    s2 = fmaf(qreg[4 * dd + 2], k4.z, s2);
                    s3 = fmaf(qreg[4 * dd + 3], k4.w, s3);
                }
                float sv = ((s0 + s1) + (s2 + s3)) * 0.125f;
                sv = (k0 + j <= q) ? sv : -1e30f;
                s[j] = sv;
                tmax = fmaxf(tmax, sv);
            }
            float mn = fmaxf(mrun, tmax);
            float corr = __expf(mrun - mn);
            lrun *= corr;
            #pragma unroll
            for (int d = 0; d < 64; d++) o[d] *= corr;
            #pragma unroll
            for (int j = 0; j < AKT; j++) {
                float p = __expf(s[j] - mn);
                lrun += p;
                const float4* vp = (const float4*)&Vs[j][0];
                #pragma unroll
                for (int dd = 0; dd < 16; dd++) {
                    float4 v4 = vp[dd];
                    o[4 * dd]     = fmaf(p, v4.x, o[4 * dd]);
                    o[4 * dd + 1] = fmaf(p, v4.y, o[4 * dd + 1]);
                    o[4 * dd + 2] = fmaf(p, v4.z, o[4 * dd + 2]);
                    o[4 * dd + 3] = fmaf(p, v4.w, o[4 * dd + 3]);
                }
            }
            mrun = mn;
        }
    }
    {
        const float inv = 1.f / lrun;
        float4* op = (float4*)(Om + base + (size_t)q * D_MODEL);
        #pragma unroll
        for (int dd = 0; dd < 16; dd++) {
            float4 t;
            t.x = o[4 * dd] * inv;     t.y = o[4 * dd + 1] * inv;
            t.z = o[4 * dd + 2] * inv; t.w = o[4 * dd + 3] * inv;
            op[dd] = t;
        }
    }
}

// ---------------- fused logits + softmax into d_out slice l ----------------
__global__ __launch_bounds__(256) void probs_kernel(const float* __restrict__ X,
                                                    const float* __restrict__ Wout,
                                                    float* __restrict__ out,
                                                    int l) {
    __shared__ float xs[8][1024];
    __shared__ float red[8][8];
    const int tid = threadIdx.x;
    const int row0 = blockIdx.x * 8;

    #pragma unroll
    for (int it = 0; it < 8; it++) {
        int idx = tid + it * 256;        // 0..2047 float4 indices
        int m = idx >> 8;
        int c4 = idx & 255;
        int gr = row0 + m;
        float4 v = make_float4(0.f, 0.f, 0.f, 0.f);
        if (gr < M_ROWS) v = ((const float4*)&X[(size_t)gr * 1024])[c4];
        ((float4*)&xs[m][0])[c4] = v;
    }
    __syncthreads();

    float acc[8];
    #pragma unroll
    for (int m = 0; m < 8; m++) acc[m] = 0.f;
    const int v = tid;
    #pragma unroll 4
    for (int k0 = 0; k0 < 1024; k0 += 4) {
        float w0 = Wout[(k0 + 0) * VOCAB + v];
        float w1 = Wout[(k0 + 1) * VOCAB + v];
        float w2 = Wout[(k0 + 2) * VOCAB + v];
        float w3 = Wout[(k0 + 3) * VOCAB + v];
        #pragma unroll
        for (int m = 0; m < 8; m++) {
            float4 x4 = *(const float4*)&xs[m][k0];
            float t0 = fmaf(x4.x, w0, acc[m]);
            float t1 = fmaf(x4.y, w1, t0);
            float t2 = fmaf(x4.z, w2, t1);
            acc[m]   = fmaf(x4.w, w3, t2);
        }
    }

    const int lane = tid & 31;
    const int wid  = tid >> 5;
    float bmax[8];
    #pragma unroll
    for (int m = 0; m < 8; m++) {
        float x = acc[m];
        #pragma unroll
        for (int off = 16; off; off >>= 1)
            x = fmaxf(x, __shfl_xor_sync(0xffffffffu, x, off));
        if (lane == 0) red[m][wid] = x;
    }
    __syncthreads();
    #pragma unroll
    for (int m = 0; m < 8; m++) {
        float mx = red[m][0];
        #pragma unroll
        for (int w = 1; w < 8; w++) mx = fmaxf(mx, red[m][w]);
        bmax[m] = mx;
    }
    __syncthreads();
    float p[8];
    #pragma unroll
    for (int m = 0; m < 8; m++) {
        p[m] = __expf(acc[m] - bmax[m]);
        float x = p[m];
        #pragma unroll
        for (int off = 16; off; off >>= 1)
            x += __shfl_xor_sync(0xffffffffu, x, off);
        if (lane == 0) red[m][wid] = x;
    }
    __syncthreads();
    #pragma unroll
    for (int m = 0; m < 8; m++) {
        float sm = 0.f;
        #pragma unroll
        for (int w = 0; w < 8; w++) sm += red[m][w];
        int gr = row0 + m;
        if (gr < M_ROWS) {
            int b = gr / N_CTX;
            int t = gr - b * N_CTX;
            out[(((size_t)l * B_SZ + b) * N_CTX + t) * VOCAB + v] = p[m] / sm;
        }
    }
}

// ---------------- orchestration ----------------
extern "C" void kernel_launch(void* const* d_in, const int* in_sizes, int n_in,
                              void* d_out, int out_size) {
    const int*   ids  = (const int*)d_in[0];
    const float* emb  = (const float*)d_in[1];
    const float* Wq   = (const float*)d_in[2];
    const float* Wk   = (const float*)d_in[3];
    const float* Wv   = (const float*)d_in[4];
    const float* Wo   = (const float*)d_in[5];
    const float* Wout = (const float*)d_in[6];
    float* out = (float*)d_out;

    float *X, *Q, *K, *V, *O;
    cudaGetSymbolAddress((void**)&X, g_X);
    cudaGetSymbolAddress((void**)&Q, g_Q);
    cudaGetSymbolAddress((void**)&K, g_K);
    cudaGetSymbolAddress((void**)&V, g_V);
    cudaGetSymbolAddress((void**)&O, g_O);

    embed_kernel<<<(M_ROWS * D_MODEL + 255) / 256, 256>>>(ids, emb);
    probs_kernel<<<(M_ROWS + 7) / 8, 256>>>(X, Wout, out, 0);

    dim3 ggrid(8, (M_ROWS + 127) / 128);
    dim3 agrid((N_CTX + 255) / 256, N_HEADS, B_SZ);
    for (int l = 0; l < N_LAYERS; l++) {
        const float* wq = Wq + (size_t)l * D_MODEL * D_MODEL;
        const float* wk = Wk + (size_t)l * D_MODEL * D_MODEL;
        const float* wv = Wv + (size_t)l * D_MODEL * D_MODEL;
        const float* wo = Wo + (size_t)l * D_MODEL * D_MODEL;
        sgemm1024<<<ggrid, 256>>>(X, wq, nullptr, Q);
        sgemm1024<<<ggrid, 256>>>(X, wk, nullptr, K);
        sgemm1024<<<ggrid, 256>>>(X, wv, nullptr, V);
        attn_kernel<<<agrid, 256>>>(Q, K, V, O);
        sgemm1024<<<ggrid, 256>>>(O, wo, X, X);   // X = X + O @ Wo
        probs_kernel<<<(M_ROWS + 7) / 8, 256>>>(X, Wout, out, l + 1);
    }
}